// round 2
// baseline (speedup 1.0000x reference)
#include <cuda_runtime.h>
#include <cstdint>
#include <cstddef>

#define IMG_B   64
#define IMG_H   32
#define IMG_W   4096
#define NSLICE  512
#define PADW    12
#define MTOT    32768
#define KTOT    1024
#define NTOT    512

// Scratch: A activations (tf32-rounded) and tf32-rounded weights.
__device__ float g_A[(size_t)MTOT * KTOT];   // 128 MB
__device__ float g_W[(size_t)KTOT * NTOT];   // 2 MB

__device__ __forceinline__ float to_tf32(float x) {
    float r;
    asm("cvt.rna.tf32.f32 %0, %1;" : "=f"(r) : "f"(x));
    return r;
}

__device__ __forceinline__ void cpa16(void* smem_ptr, const void* gptr) {
    uint32_t sa;
    asm("{ .reg .u64 t; cvta.to.shared.u64 t, %1; cvt.u32.u64 %0, t; }"
        : "=r"(sa) : "l"(smem_ptr));
    asm volatile("cp.async.cg.shared.global [%0], [%1], 16;" :: "r"(sa), "l"(gptr));
}
__device__ __forceinline__ void cpa_commit() {
    asm volatile("cp.async.commit_group;" ::: "memory");
}
__device__ __forceinline__ void cpa_wait0() {
    asm volatile("cp.async.wait_group 0;" ::: "memory");
}

// ---------------------------------------------------------------------------
// Kernel 1: slice extraction + 3x3 conv (per-slice zero pad) + bias + ReLU
// One block per (s, b). 256 threads; each computes 4 consecutive outputs.
// ---------------------------------------------------------------------------
__global__ void __launch_bounds__(256) agen(const float* __restrict__ img,
                                            const float* __restrict__ cw,
                                            const float* __restrict__ cb) {
    __shared__ float xs[34][35];
    const int s = blockIdx.x;
    const int b = blockIdx.y;
    const int t = threadIdx.x;

    const float* ib = img + (size_t)b * IMG_H * IMG_W;

    // Load 34x34 region: slice-local coords r,c in [-1,32]; zero border is the
    // conv's own zero padding; inside the slice, columns outside the image are
    // the global pad value 1.0.
    for (int idx = t; idx < 34 * 34; idx += 256) {
        const int r = idx / 34 - 1;
        const int c = idx % 34 - 1;
        float v = 0.0f;
        if ((unsigned)r < 32u && (unsigned)c < 32u) {
            const int g = s * 8 + c - PADW;
            v = ((unsigned)g < (unsigned)IMG_W) ? ib[r * IMG_W + g] : 1.0f;
        }
        xs[idx / 34][idx % 34] = v;
    }

    float w[9];
#pragma unroll
    for (int i = 0; i < 9; i++) w[i] = cw[i];
    const float bias = cb[0];

    __syncthreads();

    const int oh  = (t * 4) >> 5;   // output row 0..31
    const int ow0 = (t * 4) & 31;   // output col base (0,4,...,28)

    float4 o;
    float* op = &o.x;
#pragma unroll
    for (int j = 0; j < 4; j++) {
        const int ow = ow0 + j;
        float acc = bias;
#pragma unroll
        for (int ki = 0; ki < 3; ki++)
#pragma unroll
            for (int kj = 0; kj < 3; kj++)
                acc += w[ki * 3 + kj] * xs[oh + ki][ow + kj];
        acc = fmaxf(acc, 0.0f);
        op[j] = to_tf32(acc);
    }

    const size_t row = (size_t)b * NSLICE + s;
    *reinterpret_cast<float4*>(&g_A[row * KTOT + t * 4]) = o;
}

// ---------------------------------------------------------------------------
// Kernel 2: tf32-round lin_w into g_W (same K x N row-major layout)
// ---------------------------------------------------------------------------
__global__ void __launch_bounds__(256) prepw(const float* __restrict__ lw) {
    const int i = blockIdx.x * 256 + threadIdx.x;   // float4 index
    float4 v = reinterpret_cast<const float4*>(lw)[i];
    v.x = to_tf32(v.x); v.y = to_tf32(v.y);
    v.z = to_tf32(v.z); v.w = to_tf32(v.w);
    reinterpret_cast<float4*>(g_W)[i] = v;
}

// ---------------------------------------------------------------------------
// Kernel 3: C = A * W + b  via mma.sync m16n8k8 tf32
// Tiles: BM=128, BN=128, BK=16. 256 threads (8 warps, 2x4), warp tile 64x32.
// cp.async double buffering. Smem padded conflict-free (A stride 20, B 136).
// ---------------------------------------------------------------------------
#define ASTRIDE 20
#define BSTRIDE 136

__global__ void __launch_bounds__(256, 2) gemm(const float* __restrict__ bias,
                                               float* __restrict__ out) {
    __shared__ float As[2][128 * ASTRIDE];
    __shared__ float Bs[2][16 * BSTRIDE];

    const int t    = threadIdx.x;
    const int bx   = blockIdx.x;       // N block (0..3)
    const int by   = blockIdx.y;       // M block (0..255)
    const int warp = t >> 5;
    const int lane = t & 31;
    const int wm   = warp >> 2;        // 0..1
    const int wn   = warp & 3;         // 0..3
    const int gid  = lane >> 2;        // group id 0..7
    const int tig  = lane & 3;         // thread-in-group 0..3

    float c[4][4][4];
#pragma unroll
    for (int i = 0; i < 4; i++)
#pragma unroll
        for (int j = 0; j < 4; j++)
#pragma unroll
            for (int k = 0; k < 4; k++) c[i][j][k] = 0.0f;

    const size_t abase = (size_t)by * 128 * KTOT;
    const float* Wb = g_W + bx * 128;

    // stage loader: A tile 128x16, B tile 16x128 via cp.async (16B each)
    auto load_stage = [&](int buf, int kt) {
        const int k0 = kt * 16;
#pragma unroll
        for (int i = 0; i < 2; i++) {
            const int li  = t + i * 256;
            const int row = li >> 2;           // 0..127
            const int seg = li & 3;            // 0..3 (x4 floats)
            cpa16(&As[buf][row * ASTRIDE + seg * 4],
                  &g_A[abase + (size_t)row * KTOT + k0 + seg * 4]);
        }
#pragma unroll
        for (int i = 0; i < 2; i++) {
            const int li  = t + i * 256;
            const int row = li >> 5;           // 0..15
            const int c4  = li & 31;           // 0..31
            cpa16(&Bs[buf][row * BSTRIDE + c4 * 4],
                  &Wb[(size_t)(k0 + row) * NTOT + c4 * 4]);
        }
        cpa_commit();
    };

    load_stage(0, 0);

    const int KITERS = KTOT / 16;  // 64
    for (int kt = 0; kt < KITERS; kt++) {
        const int cur = kt & 1;
        cpa_wait0();
        __syncthreads();           // stage `cur` ready; prior reads of `cur^1` done

        if (kt + 1 < KITERS) load_stage(cur ^ 1, kt + 1);

        const float* Ab = As[cur];
        const float* Bb = Bs[cur];

#pragma unroll
        for (int ks = 0; ks < 2; ks++) {
            uint32_t a[4][4], bf[4][2];
#pragma unroll
            for (int mt = 0; mt < 4; mt++) {
                const int r  = wm * 64 + mt * 16 + gid;
                const int cc = ks * 8 + tig;
                a[mt][0] = __float_as_uint(Ab[r * ASTRIDE + cc]);
                a[mt][1] = __float_as_uint(Ab[(r + 8) * ASTRIDE + cc]);
                a[mt][2] = __float_as_uint(Ab[r * ASTRIDE + cc + 4]);
                a[mt][3] = __float_as_uint(Ab[(r + 8) * ASTRIDE + cc + 4]);
            }
#pragma unroll
            for (int nt = 0; nt < 4; nt++) {
                const int cb_ = wn * 32 + nt * 8 + gid;
                const int kr  = ks * 8 + tig;
                bf[nt][0] = __float_as_uint(Bb[kr * BSTRIDE + cb_]);
                bf[nt][1] = __float_as_uint(Bb[(kr + 4) * BSTRIDE + cb_]);
            }
#pragma unroll
            for (int mt = 0; mt < 4; mt++)
#pragma unroll
                for (int nt = 0; nt < 4; nt++) {
                    asm volatile(
                        "mma.sync.aligned.m16n8k8.row.col.f32.tf32.tf32.f32 "
                        "{%0,%1,%2,%3}, {%4,%5,%6,%7}, {%8,%9}, {%0,%1,%2,%3};"
                        : "+f"(c[mt][nt][0]), "+f"(c[mt][nt][1]),
                          "+f"(c[mt][nt][2]), "+f"(c[mt][nt][3])
                        : "r"(a[mt][0]), "r"(a[mt][1]), "r"(a[mt][2]), "r"(a[mt][3]),
                          "r"(bf[nt][0]), "r"(bf[nt][1]));
                }
        }
        __syncthreads();           // everyone done reading `cur` before it is refilled
    }

    // Epilogue: += bias, write fp32 output
#pragma unroll
    for (int mt = 0; mt < 4; mt++) {
#pragma unroll
        for (int nt = 0; nt < 4; nt++) {
            const int r0 = by * 128 + wm * 64 + mt * 16 + gid;
            const int c0 = bx * 128 + wn * 32 + nt * 8 + (tig << 1);
            const float b0 = bias[c0], b1 = bias[c0 + 1];
            float2 v0 = make_float2(c[mt][nt][0] + b0, c[mt][nt][1] + b1);
            float2 v1 = make_float2(c[mt][nt][2] + b0, c[mt][nt][3] + b1);
            *reinterpret_cast<float2*>(&out[(size_t)r0 * NTOT + c0])       = v0;
            *reinterpret_cast<float2*>(&out[(size_t)(r0 + 8) * NTOT + c0]) = v1;
        }
    }
}

// ---------------------------------------------------------------------------
extern "C" void kernel_launch(void* const* d_in, const int* in_sizes, int n_in,
                              void* d_out, int out_size) {
    const float* images = (const float*)d_in[0];
    const float* conv_w = (const float*)d_in[1];
    const float* conv_b = (const float*)d_in[2];
    const float* lin_w  = (const float*)d_in[3];
    const float* lin_b  = (const float*)d_in[4];
    float* out = (float*)d_out;

    agen<<<dim3(NSLICE, IMG_B), 256>>>(images, conv_w, conv_b);
    prepw<<<(KTOT * NTOT / 4) / 256, 256>>>(lin_w);
    gemm<<<dim3(NTOT / 128, MTOT / 128), 256>>>(lin_b, out);
}

// round 4
// speedup vs baseline: 1.1857x; 1.1857x over previous
#include <cuda_runtime.h>
#include <cstdint>
#include <cstddef>

#define IMG_B   64
#define IMG_H   32
#define IMG_W   4096
#define NSLICE  512
#define MTOT    32768
#define KTOT    1024
#define NTOT    512

// Scratch (static device arrays; no runtime allocation).
__device__ float g_A[(size_t)MTOT * KTOT];   // 128 MB activations (tf32-rounded), M x K
__device__ float g_W[(size_t)NTOT * KTOT];   // 2 MB  W^T (tf32-rounded), N x K

// ---------------------------------------------------------------------------
// helpers
// ---------------------------------------------------------------------------
__device__ __forceinline__ float to_tf32(float x) {
    float r;
    asm("cvt.rna.tf32.f32 %0, %1;" : "=f"(r) : "f"(x));
    return r;
}

__device__ __forceinline__ uint32_t smem_u32(const void* p) {
    uint32_t a;
    asm("{ .reg .u64 t; cvta.to.shared.u64 t, %1; cvt.u32.u64 %0, t; }" : "=r"(a) : "l"(p));
    return a;
}

__device__ __forceinline__ void cpa16(uint32_t smem_addr, const void* gptr) {
    asm volatile("cp.async.cg.shared.global [%0], [%1], 16;" :: "r"(smem_addr), "l"(gptr));
}
__device__ __forceinline__ void cpa_commit() {
    asm volatile("cp.async.commit_group;" ::: "memory");
}

__device__ __forceinline__ void ldsm_x4(uint32_t r[4], uint32_t addr) {
    asm volatile("ldmatrix.sync.aligned.m8n8.x4.shared.b16 {%0,%1,%2,%3}, [%4];"
                 : "=r"(r[0]), "=r"(r[1]), "=r"(r[2]), "=r"(r[3]) : "r"(addr));
}

// ---------------------------------------------------------------------------
// Kernel 1: slice extraction + 3x3 conv (slice-local zero pad, global 1.0 pad)
//           + bias + ReLU + tf32 round -> g_A
// Grid: (2 halves, IMG_H, IMG_B), 256 threads. Thread t owns slice
// s = half*256 + t and computes its 32 outputs for image row h.
// ---------------------------------------------------------------------------
#define AG_SPAN 2112
#define AG_PHYS (AG_SPAN + AG_SPAN / 32)   // +1 pad float per 32 -> conflict-free

__global__ void __launch_bounds__(256) agen(const float* __restrict__ img,
                                            const float* __restrict__ cw,
                                            const float* __restrict__ cb) {
    __shared__ float xs[3][AG_PHYS];

    const int half = blockIdx.x;
    const int h    = blockIdx.y;
    const int b    = blockIdx.z;
    const int t    = threadIdx.x;

    const int O = half * 2048 - 16;        // logical-col origin of this strip
    const float* ib = img + (size_t)b * IMG_H * IMG_W;

    // Fill 3 rows (h-1, h, h+1). Out-of-range rows -> 0 (vertical conv pad);
    // in-range rows: out-of-image columns -> 1.0 (global pad value).
#pragma unroll
    for (int r3 = 0; r3 < 3; r3++) {
        const int inrow = h + r3 - 1;
        const bool rowok = (unsigned)inrow < 32u;
        const float* rp = ib + inrow * IMG_W;
        for (int rel = t; rel < AG_SPAN; rel += 256) {
            const int g = O + rel;
            float v = 0.0f;
            if (rowok) v = ((unsigned)g < (unsigned)IMG_W) ? rp[g] : 1.0f;
            xs[r3][rel + (rel >> 5)] = v;
        }
    }

    float w[3][3];
#pragma unroll
    for (int i = 0; i < 3; i++)
#pragma unroll
        for (int j = 0; j < 3; j++) w[i][j] = cw[i * 3 + j];
    const float bias = cb[0];

    __syncthreads();

    float acc[32];
#pragma unroll
    for (int c = 0; c < 32; c++) acc[c] = bias;

    // slice col cc maps to rel = 8t + 4 + cc  (s*8 - 12 - O = 8t + 4)
#pragma unroll
    for (int r3 = 0; r3 < 3; r3++) {
        const float w0 = w[r3][0], w1 = w[r3][1], w2 = w[r3][2];
#pragma unroll
        for (int cc = 0; cc < 32; cc++) {
            const int rel = 8 * t + 4 + cc;
            const float xv = xs[r3][rel + (rel >> 5)];
            acc[cc] += w1 * xv;
            if (cc > 0)  acc[cc - 1] += w2 * xv;
            if (cc < 31) acc[cc + 1] += w0 * xv;
        }
    }

    const int s = half * 256 + t;
    float* op = g_A + ((size_t)(b * NSLICE + s)) * KTOT + h * 32;
#pragma unroll
    for (int c = 0; c < 32; c += 4) {
        float4 v;
        v.x = to_tf32(fmaxf(acc[c + 0], 0.0f));
        v.y = to_tf32(fmaxf(acc[c + 1], 0.0f));
        v.z = to_tf32(fmaxf(acc[c + 2], 0.0f));
        v.w = to_tf32(fmaxf(acc[c + 3], 0.0f));
        *reinterpret_cast<float4*>(op + c) = v;
    }
}

// ---------------------------------------------------------------------------
// Kernel 2: g_W[n][k] = tf32(lin_w[k][n])   (transpose + round)
// ---------------------------------------------------------------------------
__global__ void __launch_bounds__(256) prepw(const float* __restrict__ lw) {
    __shared__ float tl[32][33];
    const int tx = threadIdx.x & 31;
    const int ty = threadIdx.x >> 5;      // 0..7
    const int n0 = blockIdx.x * 32;
    const int k0 = blockIdx.y * 32;
#pragma unroll
    for (int i = 0; i < 4; i++)
        tl[ty + 8 * i][tx] = lw[(size_t)(k0 + ty + 8 * i) * NTOT + n0 + tx];
    __syncthreads();
#pragma unroll
    for (int i = 0; i < 4; i++)
        g_W[(size_t)(n0 + ty + 8 * i) * KTOT + k0 + tx] = to_tf32(tl[tx][ty + 8 * i]);
}

// ---------------------------------------------------------------------------
// Kernel 3: tf32 GEMM via mma.sync m16n8k8 + ldmatrix.
// CTA tile 128(M) x 256(N), BK=32. 256 threads, warp grid 2x4, warp tile 64x64.
// 3-stage cp.async pipeline. XOR-swizzled smem (seg ^= row&7): conflict-free
// for both the cp.async stores and ldmatrix reads.
//   A stage: 128 rows x 128B = 16 KB   (rows = M, 32 tf32 k-cols)
//   B stage: 256 rows x 128B = 32 KB   (rows = N, 32 tf32 k-cols)
// ---------------------------------------------------------------------------
#define STAGES      3
#define STAGE_BYTES 49152                 // 16 KB A + 32 KB B
#define GEMM_SMEM   (STAGES * STAGE_BYTES)
#define KCHUNKS     (KTOT / 32)           // 32

__global__ void __launch_bounds__(256) gemm(const float* __restrict__ bias,
                                            float* __restrict__ out) {
    extern __shared__ __align__(1024) char dsm[];

    const int t    = threadIdx.x;
    const int lane = t & 31;
    const int warp = t >> 5;
    const int wm   = warp >> 2;     // 0..1
    const int wn   = warp & 3;      // 0..3
    const int bx   = blockIdx.x;    // N block (0..1)
    const int by   = blockIdx.y;    // M block (0..255)

    const uint32_t smem_base = smem_u32(dsm);

    const char* Agc = (const char*)(g_A + (size_t)(by * 128) * KTOT);
    const char* Bgc = (const char*)(g_W + (size_t)(bx * 256) * KTOT);

    // per-thread cp.async assignments (row, chunk) with XOR swizzle
    auto load_chunk = [&](int stage, int kc) {
        const uint32_t sa = smem_base + stage * STAGE_BYTES;
        const uint32_t sb = sa + 16384;
        const size_t kofs = (size_t)kc * 128;     // bytes into each 4096B K-row
#pragma unroll
        for (int i = 0; i < 4; i++) {             // A: 1024 chunks
            const int id = t + i * 256;
            const int row = id >> 3, ch = id & 7;
            cpa16(sa + row * 128 + ((ch ^ (row & 7)) << 4),
                  Agc + (size_t)row * 4096 + kofs + ch * 16);
        }
#pragma unroll
        for (int i = 0; i < 8; i++) {             // B: 2048 chunks
            const int id = t + i * 256;
            const int row = id >> 3, ch = id & 7;
            cpa16(sb + row * 128 + ((ch ^ (row & 7)) << 4),
                  Bgc + (size_t)row * 4096 + kofs + ch * 16);
        }
        cpa_commit();
    };

    float c[4][8][4];
#pragma unroll
    for (int i = 0; i < 4; i++)
#pragma unroll
        for (int j = 0; j < 8; j++)
#pragma unroll
            for (int k = 0; k < 4; k++) c[i][j][k] = 0.0f;

    load_chunk(0, 0);
    load_chunk(1, 1);
    load_chunk(2, 2);

    // ldmatrix per-lane address components
    const int rm      = lane & 7;                       // XOR key (row & 7)
    const int a_roff  = (wm * 64 + (lane & 15)) * 128;  // + mt*2048
    const int a_m     = lane >> 4;                      // seg parity
    const int b_roff  = (wn * 64 + ((lane >> 4) << 3) + (lane & 7)) * 128; // + p*2048
    const int b_m     = (lane >> 3) & 1;

    for (int kc = 0; kc < KCHUNKS; kc++) {
        const int cur = kc % STAGES;
        if (kc < KCHUNKS - 2)
            asm volatile("cp.async.wait_group 2;" ::: "memory");
        else if (kc == KCHUNKS - 2)
            asm volatile("cp.async.wait_group 1;" ::: "memory");
        else
            asm volatile("cp.async.wait_group 0;" ::: "memory");
        __syncthreads();

        const uint32_t sa = smem_base + cur * STAGE_BYTES;
        const uint32_t sb = sa + 16384;

#pragma unroll
        for (int ks = 0; ks < 4; ks++) {
            uint32_t a[4][4], bfr[4][4];
#pragma unroll
            for (int mt = 0; mt < 4; mt++)
                ldsm_x4(a[mt], sa + a_roff + mt * 2048 +
                               (((2 * ks + a_m) ^ rm) << 4));
#pragma unroll
            for (int p = 0; p < 4; p++)
                ldsm_x4(bfr[p], sb + b_roff + p * 2048 +
                                (((2 * ks + b_m) ^ rm) << 4));
#pragma unroll
            for (int mt = 0; mt < 4; mt++)
#pragma unroll
                for (int p = 0; p < 4; p++) {
                    asm volatile(
                        "mma.sync.aligned.m16n8k8.row.col.f32.tf32.tf32.f32 "
                        "{%0,%1,%2,%3}, {%4,%5,%6,%7}, {%8,%9}, {%0,%1,%2,%3};"
                        : "+f"(c[mt][2 * p][0]), "+f"(c[mt][2 * p][1]),
                          "+f"(c[mt][2 * p][2]), "+f"(c[mt][2 * p][3])
                        : "r"(a[mt][0]), "r"(a[mt][1]), "r"(a[mt][2]), "r"(a[mt][3]),
                          "r"(bfr[p][0]), "r"(bfr[p][1]));
                    asm volatile(
                        "mma.sync.aligned.m16n8k8.row.col.f32.tf32.tf32.f32 "
                        "{%0,%1,%2,%3}, {%4,%5,%6,%7}, {%8,%9}, {%0,%1,%2,%3};"
                        : "+f"(c[mt][2 * p + 1][0]), "+f"(c[mt][2 * p + 1][1]),
                          "+f"(c[mt][2 * p + 1][2]), "+f"(c[mt][2 * p + 1][3])
                        : "r"(a[mt][0]), "r"(a[mt][1]), "r"(a[mt][2]), "r"(a[mt][3]),
                          "r"(bfr[p][2]), "r"(bfr[p][3]));
                }
        }
        __syncthreads();
        if (kc + STAGES < KCHUNKS) load_chunk(cur, kc + STAGES);
    }

    // Epilogue: += bias, write fp32 output
#pragma unroll
    for (int nt = 0; nt < 8; nt++) {
        const int col = bx * 256 + wn * 64 + nt * 8 + 2 * (lane & 3);
        const float b0 = bias[col], b1 = bias[col + 1];
#pragma unroll
        for (int mt = 0; mt < 4; mt++) {
            const int r0 = by * 128 + wm * 64 + mt * 16 + (lane >> 2);
            float2 v0 = make_float2(c[mt][nt][0] + b0, c[mt][nt][1] + b1);
            float2 v1 = make_float2(c[mt][nt][2] + b0, c[mt][nt][3] + b1);
            *reinterpret_cast<float2*>(&out[(size_t)r0 * NTOT + col])       = v0;
            *reinterpret_cast<float2*>(&out[(size_t)(r0 + 8) * NTOT + col]) = v1;
        }
    }
}

// ---------------------------------------------------------------------------
extern "C" void kernel_launch(void* const* d_in, const int* in_sizes, int n_in,
                              void* d_out, int out_size) {
    const float* images = (const float*)d_in[0];
    const float* conv_w = (const float*)d_in[1];
    const float* conv_b = (const float*)d_in[2];
    const float* lin_w  = (const float*)d_in[3];
    const float* lin_b  = (const float*)d_in[4];
    float* out = (float*)d_out;

    cudaFuncSetAttribute(gemm, cudaFuncAttributeMaxDynamicSharedMemorySize,
                         GEMM_SMEM);

    agen<<<dim3(2, IMG_H, IMG_B), 256>>>(images, conv_w, conv_b);
    prepw<<<dim3(NTOT / 32, KTOT / 32), 256>>>(lin_w);
    gemm<<<dim3(NTOT / 256, MTOT / 128), 256, GEMM_SMEM>>>(lin_b, out);
}